// round 4
// baseline (speedup 1.0000x reference)
#include <cuda_runtime.h>

// DCT band decomposition: x[16,3,512,512] f32 -> (low, mid, high) concatenated.
// One thread per 8x8 block. DCT matrix folded to FFMA immediates.
// high band = residual (x - low_u - mid_u) * s2; x rows re-read from L1.

namespace {
constexpr int BATCH = 16, CHAN = 3, H = 512, W = 512;
constexpr int NPIX = BATCH * CHAN * H * W;                 // 12582912
constexpr int NBLOCKS = BATCH * CHAN * (H / 8) * (W / 8);  // 196608
constexpr int TPB = 128;
}

// Orthonormal 8-point DCT-II matrix: constexpr so every access folds to a
// compile-time literal -> FFMA imm-form (rt_SMSP=1, no LDC on Blackwell).
__host__ __device__ constexpr float Dv(int k, int t) {
    constexpr float A4 = 0.3535533905932738f;
    constexpr float C1 = 0.4903926402016152f;
    constexpr float C2 = 0.4619397662556434f;
    constexpr float C3 = 0.4157348061512726f;
    constexpr float C5 = 0.2777851165098011f;
    constexpr float C6 = 0.1913417161825449f;
    constexpr float C7 = 0.0975451610080641f;
    constexpr float m[8][8] = {
        { A4,  A4,  A4,  A4,  A4,  A4,  A4,  A4},
        { C1,  C3,  C5,  C7, -C7, -C5, -C3, -C1},
        { C2,  C6, -C6, -C2, -C2, -C6,  C6,  C2},
        { C3, -C7, -C1, -C5,  C5,  C1,  C7, -C3},
        { A4, -A4, -A4,  A4,  A4, -A4, -A4,  A4},
        { C5, -C1,  C7,  C3, -C3, -C7,  C1, -C5},
        { C6, -C2,  C2, -C6, -C6,  C2, -C2,  C6},
        { C7, -C5,  C3, -C1,  C1, -C3,  C5, -C7}
    };
    return m[k][t];
}

// Zigzag bands: low = zz<21 <=> k+l<=5 ; mid = 21<=zz<42 <=> 6<=k+l<=8 \ (1,7)
__host__ __device__ constexpr bool in_low(int k, int l) { return k + l <= 5; }
__host__ __device__ constexpr bool in_mid(int k, int l) {
    const int s = k + l;
    return (s >= 6 && s <= 8) && !(k == 1 && l == 7);
}

__global__ void __launch_bounds__(TPB, 5)
dct_decomp_kernel(const float* __restrict__ x,
                  const float* __restrict__ band_scale,
                  float* __restrict__ out)
{
    const int tid = blockIdx.x * TPB + threadIdx.x;   // grid sized exactly
    const int bw = tid & 63;          // block col (W/8 = 64)
    const int bh = (tid >> 6) & 63;   // block row
    const int bc = tid >> 12;         // fused batch*chan 0..47

    const size_t base = ((size_t)bc * H + (size_t)bh * 8) * W + (size_t)bw * 8;
    const float* src = x + base;

    const float s0 = __ldg(band_scale + 0);
    const float s1 = __ldg(band_scale + 1);
    const float s2 = __ldg(band_scale + 2);

    // ---- Load 8x8 block (16 independent LDG.128, front-batched) ----
    float C[8][8];
#pragma unroll
    for (int r = 0; r < 8; r++) {
        float4 a = *reinterpret_cast<const float4*>(src + (size_t)r * W);
        float4 b = *reinterpret_cast<const float4*>(src + (size_t)r * W + 4);
        C[r][0] = a.x; C[r][1] = a.y; C[r][2] = a.z; C[r][3] = a.w;
        C[r][4] = b.x; C[r][5] = b.y; C[r][6] = b.z; C[r][7] = b.w;
    }

    // ---- Forward 2D DCT in place: C <- D X D^T ----
#pragma unroll
    for (int t = 0; t < 8; t++) {     // column pass
        float tmp[8];
#pragma unroll
        for (int k = 0; k < 8; k++) {
            float s = 0.0f;
#pragma unroll
            for (int m = 0; m < 8; m++)
                s = fmaf(C[m][t], Dv(k, m), s);
            tmp[k] = s;
        }
#pragma unroll
        for (int k = 0; k < 8; k++) C[k][t] = tmp[k];
    }
#pragma unroll
    for (int k = 0; k < 8; k++) {     // row pass
        float tmp[8];
#pragma unroll
        for (int l = 0; l < 8; l++) {
            float s = 0.0f;
#pragma unroll
            for (int t = 0; t < 8; t++)
                s = fmaf(C[k][t], Dv(l, t), s);
            tmp[l] = s;
        }
#pragma unroll
        for (int l = 0; l < 8; l++) C[k][l] = tmp[l];
    }

    float* dst_low  = out + base;
    float* dst_mid  = out + (size_t)NPIX + base;
    float* dst_high = out + 2 * (size_t)NPIX + base;

    // ---- Row-streamed band reconstruction ----
#pragma unroll
    for (int m = 0; m < 8; m++) {
        // -- low band (unscaled kept for residual) --
        float lrow[8];
        {
            float yl[6];
#pragma unroll
            for (int l = 0; l < 6; l++) {      // cols 6,7 have no low coeffs
                float s = 0.0f;
#pragma unroll
                for (int k = 0; k < 8; k++)
                    if (in_low(k, l))
                        s = fmaf(C[k][l], Dv(k, m), s);
                yl[l] = s;
            }
#pragma unroll
            for (int n = 0; n < 8; n++) {
                float s = 0.0f;
#pragma unroll
                for (int l = 0; l < 6; l++)
                    s = fmaf(yl[l], Dv(l, n), s);
                lrow[n] = s;
            }
        }
        *reinterpret_cast<float4*>(dst_low + m * W) =
            make_float4(lrow[0] * s0, lrow[1] * s0, lrow[2] * s0, lrow[3] * s0);
        *reinterpret_cast<float4*>(dst_low + m * W + 4) =
            make_float4(lrow[4] * s0, lrow[5] * s0, lrow[6] * s0, lrow[7] * s0);

        // -- mid band (unscaled kept for residual) --
        float mrow[8];
        {
            float ym[8];
#pragma unroll
            for (int l = 0; l < 8; l++) {
                float s = 0.0f;
#pragma unroll
                for (int k = 0; k < 8; k++)
                    if (in_mid(k, l))
                        s = fmaf(C[k][l], Dv(k, m), s);
                ym[l] = s;
            }
#pragma unroll
            for (int n = 0; n < 8; n++) {
                float s = 0.0f;
#pragma unroll
                for (int l = 0; l < 8; l++)
                    s = fmaf(ym[l], Dv(l, n), s);
                mrow[n] = s;
            }
        }
        *reinterpret_cast<float4*>(dst_mid + m * W) =
            make_float4(mrow[0] * s1, mrow[1] * s1, mrow[2] * s1, mrow[3] * s1);
        *reinterpret_cast<float4*>(dst_mid + m * W + 4) =
            make_float4(mrow[4] * s1, mrow[5] * s1, mrow[6] * s1, mrow[7] * s1);

        // -- high band = (x - low_u - mid_u) * s2 ; x row re-read (L1 hit) --
        float4 xa = *reinterpret_cast<const float4*>(src + (size_t)m * W);
        float4 xb = *reinterpret_cast<const float4*>(src + (size_t)m * W + 4);
        *reinterpret_cast<float4*>(dst_high + m * W) = make_float4(
            (xa.x - lrow[0] - mrow[0]) * s2, (xa.y - lrow[1] - mrow[1]) * s2,
            (xa.z - lrow[2] - mrow[2]) * s2, (xa.w - lrow[3] - mrow[3]) * s2);
        *reinterpret_cast<float4*>(dst_high + m * W + 4) = make_float4(
            (xb.x - lrow[4] - mrow[4]) * s2, (xb.y - lrow[5] - mrow[5]) * s2,
            (xb.z - lrow[6] - mrow[6]) * s2, (xb.w - lrow[7] - mrow[7]) * s2);
    }
}

extern "C" void kernel_launch(void* const* d_in, const int* in_sizes, int n_in,
                              void* d_out, int out_size)
{
    const float* x  = (const float*)d_in[0];
    const float* bs = (const float*)d_in[1];
    float* out = (float*)d_out;

    const int grid = NBLOCKS / TPB;   // 1536
    dct_decomp_kernel<<<grid, TPB>>>(x, bs, out);
}

// round 5
// speedup vs baseline: 1.2024x; 1.2024x over previous
#include <cuda_runtime.h>

// DCT band decomposition: x[16,3,512,512] f32 -> (low, mid, high) concatenated.
// One thread per 8x8 block. Butterfly forward DCT; band IDCTs exploit
// m/(7-m) and n/(7-n) cosine symmetry. DCT constants fold to FFMA immediates.

namespace {
constexpr int BATCH = 16, CHAN = 3, H = 512, W = 512;
constexpr int NPIX = BATCH * CHAN * H * W;                 // 12582912
constexpr int NBLOCKS = BATCH * CHAN * (H / 8) * (W / 8);  // 196608
constexpr int TPB = 128;
}

#define A4f 0.3535533905932738f
#define C1f 0.4903926402016152f
#define C2f 0.4619397662556434f
#define C3f 0.4157348061512726f
#define C5f 0.2777851165098011f
#define C6f 0.1913417161825449f
#define C7f 0.0975451610080641f

// Orthonormal 8-point DCT-II matrix (compile-time literals after unroll).
__host__ __device__ constexpr float Dv(int k, int t) {
    constexpr float m[8][8] = {
        { A4f,  A4f,  A4f,  A4f,  A4f,  A4f,  A4f,  A4f},
        { C1f,  C3f,  C5f,  C7f, -C7f, -C5f, -C3f, -C1f},
        { C2f,  C6f, -C6f, -C2f, -C2f, -C6f,  C6f,  C2f},
        { C3f, -C7f, -C1f, -C5f,  C5f,  C1f,  C7f, -C3f},
        { A4f, -A4f, -A4f,  A4f,  A4f, -A4f, -A4f,  A4f},
        { C5f, -C1f,  C7f,  C3f, -C3f, -C7f,  C1f, -C5f},
        { C6f, -C2f,  C2f, -C6f, -C6f,  C2f, -C2f,  C6f},
        { C7f, -C5f,  C3f, -C1f,  C1f, -C3f,  C5f, -C7f}
    };
    return m[k][t];
}

// Zigzag bands: low = zz<21 <=> k+l<=5 ; mid = 21<=zz<42 <=> 6<=k+l<=8 \ (1,7)
__host__ __device__ constexpr bool in_band(int band, int k, int l) {
    const int s = k + l;
    const bool low = (s <= 5);
    const bool mid = (s >= 6 && s <= 8) && !(k == 1 && l == 7);
    if (band == 0) return low;
    if (band == 1) return mid;
    return !low && !mid;
}
__host__ __device__ constexpr bool col_active(int band, int l) {
    bool a = false;
    for (int k = 0; k < 8; k++) if (in_band(band, k, l)) a = true;
    return a;
}

// Fast 8-point DCT-II (orthonormal) on 8 values in place.
__device__ __forceinline__ void dct8(float& x0, float& x1, float& x2, float& x3,
                                     float& x4, float& x5, float& x6, float& x7)
{
    const float e0 = x0 + x7, e1 = x1 + x6, e2 = x2 + x5, e3 = x3 + x4;
    const float o0 = x0 - x7, o1 = x1 - x6, o2 = x2 - x5, o3 = x3 - x4;
    const float f0 = e0 + e3, f1 = e1 + e2;
    const float g0 = e0 - e3, g1 = e1 - e2;
    x0 = A4f * (f0 + f1);
    x4 = A4f * (f0 - f1);
    x2 = fmaf(C2f, g0,  C6f * g1);
    x6 = fmaf(C6f, g0, -C2f * g1);
    x1 = fmaf(C1f, o0, fmaf( C3f, o1, fmaf( C5f, o2,  C7f * o3)));
    x3 = fmaf(C3f, o0, fmaf(-C7f, o1, fmaf(-C1f, o2, -C5f * o3)));
    x5 = fmaf(C5f, o0, fmaf(-C1f, o1, fmaf( C7f, o2,  C3f * o3)));
    x7 = fmaf(C7f, o0, fmaf(-C5f, o1, fmaf( C3f, o2, -C1f * o3)));
}

// Stage 2 of masked IDCT: given y[l] = scaled Z[m][l], produce spatial row
// o[n] = sum_l y[l]*Dv(l,n), using n/(7-n) even/odd symmetry, then store.
template <int BAND>
__device__ __forceinline__ void idct_row_store(const float y[8],
                                               float* __restrict__ dst)
{
    float o[8];
#pragma unroll
    for (int n = 0; n < 4; n++) {
        float E = 0.0f, O = 0.0f;
#pragma unroll
        for (int l = 0; l < 8; l += 2)
            if (col_active(BAND, l)) E = fmaf(y[l], Dv(l, n), E);
#pragma unroll
        for (int l = 1; l < 8; l += 2)
            if (col_active(BAND, l)) O = fmaf(y[l], Dv(l, n), O);
        o[n]     = E + O;
        o[7 - n] = E - O;
    }
    __stcs(reinterpret_cast<float4*>(dst),
           make_float4(o[0], o[1], o[2], o[3]));
    __stcs(reinterpret_cast<float4*>(dst + 4),
           make_float4(o[4], o[5], o[6], o[7]));
}

// Masked inverse DCT of one band, processed as row pairs (m, 7-m):
// Dv(k,7-m) = (-1)^k Dv(k,m), so stage-1 even/odd-k partial sums are shared.
template <int BAND>
__device__ __forceinline__ void band_idct(const float C[8][8], float scale,
                                          float* __restrict__ dst)
{
#pragma unroll
    for (int m = 0; m < 4; m++) {
        float yA[8], yB[8];
#pragma unroll
        for (int l = 0; l < 8; l++) {
            if (col_active(BAND, l)) {
                float se = 0.0f, so = 0.0f;
#pragma unroll
                for (int k = 0; k < 8; k += 2)
                    if (in_band(BAND, k, l)) se = fmaf(C[k][l], Dv(k, m), se);
#pragma unroll
                for (int k = 1; k < 8; k += 2)
                    if (in_band(BAND, k, l)) so = fmaf(C[k][l], Dv(k, m), so);
                yA[l] = (se + so) * scale;   // row m
                yB[l] = (se - so) * scale;   // row 7-m
            } else {
                yA[l] = 0.0f; yB[l] = 0.0f;
            }
        }
        idct_row_store<BAND>(yA, dst + (size_t)m * W);
        idct_row_store<BAND>(yB, dst + (size_t)(7 - m) * W);
    }
}

__global__ void __launch_bounds__(TPB, 5)
dct_decomp_kernel(const float* __restrict__ x,
                  const float* __restrict__ band_scale,
                  float* __restrict__ out)
{
    const int tid = blockIdx.x * TPB + threadIdx.x;   // grid sized exactly
    const int bw = tid & 63;          // block col (W/8 = 64)
    const int bh = (tid >> 6) & 63;   // block row
    const int bc = tid >> 12;         // fused batch*chan 0..47

    const size_t base = ((size_t)bc * H + (size_t)bh * 8) * W + (size_t)bw * 8;
    const float* src = x + base;

    const float s0 = __ldg(band_scale + 0);
    const float s1 = __ldg(band_scale + 1);
    const float s2 = __ldg(band_scale + 2);

    // ---- Load 8x8 block (16 independent LDG.128, streaming) ----
    float C[8][8];
#pragma unroll
    for (int r = 0; r < 8; r++) {
        float4 a = __ldcs(reinterpret_cast<const float4*>(src + (size_t)r * W));
        float4 b = __ldcs(reinterpret_cast<const float4*>(src + (size_t)r * W + 4));
        C[r][0] = a.x; C[r][1] = a.y; C[r][2] = a.z; C[r][3] = a.w;
        C[r][4] = b.x; C[r][5] = b.y; C[r][6] = b.z; C[r][7] = b.w;
    }

    // ---- Forward 2D DCT in place: columns then rows, butterflied ----
#pragma unroll
    for (int t = 0; t < 8; t++)
        dct8(C[0][t], C[1][t], C[2][t], C[3][t],
             C[4][t], C[5][t], C[6][t], C[7][t]);
#pragma unroll
    for (int k = 0; k < 8; k++)
        dct8(C[k][0], C[k][1], C[k][2], C[k][3],
             C[k][4], C[k][5], C[k][6], C[k][7]);

    // ---- Three masked inverse DCTs ----
    band_idct<0>(C, s0, out + base);
    band_idct<1>(C, s1, out + (size_t)NPIX + base);
    band_idct<2>(C, s2, out + 2 * (size_t)NPIX + base);
}

extern "C" void kernel_launch(void* const* d_in, const int* in_sizes, int n_in,
                              void* d_out, int out_size)
{
    const float* x  = (const float*)d_in[0];
    const float* bs = (const float*)d_in[1];
    float* out = (float*)d_out;

    const int grid = NBLOCKS / TPB;   // 1536
    dct_decomp_kernel<<<grid, TPB>>>(x, bs, out);
}